// round 14
// baseline (speedup 1.0000x reference)
#include <cuda_runtime.h>
#include <cuda_fp16.h>
#include <math.h>
#include <stdint.h>

#define T_TOK 16384
#define DH 768
#define FF 2048
#define NE 8
#define BM 128
#define BK 64
#define NS 3
#define STAGE_B 32768                 /* A 16KB + B 16KB per stage */
#define NTHR 256                      /* 8 warps, 64x32 warp tile, 2 CTA/SM */
#define MAXROWS (2*T_TOK + NE*BM)     /* 33792 */
#define MTILES  (MAXROWS/BM)          /* 264 */

// ---------------- scratch ----------------
__device__ __align__(256) __half g_Acth[(size_t)T_TOK * FF];
__device__ __align__(256) __half g_Hrh [(size_t)MAXROWS * FF];
__device__ __align__(256) __half g_Yh  [(size_t)MAXROWS * DH];
// fp16 operand copies
__device__ __align__(256) __half g_xh  [(size_t)T_TOK * DH];
__device__ __align__(256) __half g_fc1h[(size_t)NE * FF * DH];
__device__ __align__(256) __half g_fc2h[(size_t)NE * DH * FF];
__device__ __align__(256) __half g_w1h [(size_t)FF * DH];
__device__ __align__(256) __half g_w3h [(size_t)FF * DH];
__device__ __align__(256) __half g_w2h [(size_t)DH * FF];
__device__ int   g_rowtok[MAXROWS];
__device__ float g_roww  [MAXROWS];
__device__ int   g_tok_e [2*T_TOK];
__device__ float g_tok_w [2*T_TOK];
__device__ int   g_tok_slot[2*T_TOK];
__device__ int   g_cnt   [NE];
__device__ int   g_cursor[NE];
__device__ int   g_poff  [NE+1];
__device__ int   g_ptotal;
__device__ int   g_done;

__device__ __forceinline__ float gelu_f(float v) {
    return 0.5f * v * (1.0f + erff(v * 0.7071067811865476f));
}

// ---------------- PTX helpers (sm_75+/sm_80+ only: family-target-safe) ----------------
__device__ __forceinline__ uint32_t smem_u32(const void* p) {
    uint32_t a;
    asm("{ .reg .u64 t; cvta.to.shared.u64 t, %1; cvt.u32.u64 %0, t; }" : "=r"(a) : "l"(p));
    return a;
}
__device__ __forceinline__ void cpa16(uint32_t dst, const void* src) {
    asm volatile("cp.async.cg.shared.global [%0], [%1], 16;" :: "r"(dst), "l"(src));
}
__device__ __forceinline__ void cpa_commit() { asm volatile("cp.async.commit_group;"); }
template<int N> __device__ __forceinline__ void cpa_wait() { asm volatile("cp.async.wait_group %0;" :: "n"(N)); }

#define LDSM_X4(r0, r1, r2, r3, addr) \
    asm volatile("ldmatrix.sync.aligned.m8n8.x4.shared.b16 {%0,%1,%2,%3}, [%4];" \
        : "=r"(r0), "=r"(r1), "=r"(r2), "=r"(r3) : "r"(addr))

#define MMA_F16(d, a, b) \
    asm volatile("mma.sync.aligned.m16n8k16.row.col.f32.f16.f16.f32 " \
        "{%0,%1,%2,%3}, {%4,%5,%6,%7}, {%8,%9}, {%0,%1,%2,%3};" \
        : "+f"((d)[0]), "+f"((d)[1]), "+f"((d)[2]), "+f"((d)[3]) \
        : "r"((a)[0]), "r"((a)[1]), "r"((a)[2]), "r"((a)[3]), "r"((b)[0]), "r"((b)[1]))

// ---------------- small kernels ----------------
// preconv + init fused: fp32 -> fp16 operand conversion + routing-scratch reset.
#define PC_N0 (T_TOK*DH/4)
#define PC_N1 (PC_N0 + NE*FF*DH/4)
#define PC_N2 (PC_N1 + NE*DH*FF/4)
#define PC_N3 (PC_N2 + FF*DH/4)
#define PC_N4 (PC_N3 + FF*DH/4)
#define PC_N5 (PC_N4 + DH*FF/4)
__global__ void preconv_kernel(const float4* __restrict__ x,  const float4* __restrict__ fc1,
                               const float4* __restrict__ fc2, const float4* __restrict__ w1,
                               const float4* __restrict__ w3,  const float4* __restrict__ w2) {
    int g0 = blockIdx.x * blockDim.x + threadIdx.x;
    if (g0 < MAXROWS) { g_rowtok[g0] = 0; g_roww[g0] = 0.0f; }
    if (g0 < NE) g_cnt[g0] = 0;
    if (g0 == 0) g_done = 0;
    for (long i = g0; i < PC_N5; i += (long)gridDim.x * blockDim.x) {
        const float4* src; half2* dst; long j;
        if (i < PC_N0)      { src = x;   dst = (half2*)g_xh;   j = i; }
        else if (i < PC_N1) { src = fc1; dst = (half2*)g_fc1h; j = i - PC_N0; }
        else if (i < PC_N2) { src = fc2; dst = (half2*)g_fc2h; j = i - PC_N1; }
        else if (i < PC_N3) { src = w1;  dst = (half2*)g_w1h;  j = i - PC_N2; }
        else if (i < PC_N4) { src = w3;  dst = (half2*)g_w3h;  j = i - PC_N3; }
        else                { src = w2;  dst = (half2*)g_w2h;  j = i - PC_N4; }
        float4 v = src[j];
        dst[j*2]   = __floats2half2_rn(v.x, v.y);
        dst[j*2+1] = __floats2half2_rn(v.z, v.w);
    }
}

// gate + fused scan (last block computes padded segment offsets)
__global__ void gate_kernel(const float* __restrict__ x, const float* __restrict__ gw) {
    int gtid = blockIdx.x * blockDim.x + threadIdx.x;
    int t = gtid >> 5, lane = gtid & 31;
    if (t < T_TOK) {
        const float* xr = x + (size_t)t * DH;
        float acc[NE];
#pragma unroll
        for (int e = 0; e < NE; e++) acc[e] = 0.0f;
        for (int i = lane; i < DH; i += 32) {
            float xv = xr[i];
#pragma unroll
            for (int e = 0; e < NE; e++) acc[e] = fmaf(xv, gw[e*DH + i], acc[e]);
        }
#pragma unroll
        for (int e = 0; e < NE; e++) {
#pragma unroll
            for (int o = 16; o > 0; o >>= 1) acc[e] += __shfl_xor_sync(0xffffffffu, acc[e], o);
        }
        if (lane == 0) {
            int i0 = 0;
#pragma unroll
            for (int e = 1; e < NE; e++) if (acc[e] > acc[i0]) i0 = e;
            int i1 = (i0 == 0) ? 1 : 0;
#pragma unroll
            for (int e = 0; e < NE; e++) if (e != i0 && acc[e] > acc[i1]) i1 = e;
            float e1 = expf(acc[i1] - acc[i0]);
            float inv = 1.0f / (1.0f + e1);
            g_tok_e[2*t]   = i0;  g_tok_w[2*t]   = inv;
            g_tok_e[2*t+1] = i1;  g_tok_w[2*t+1] = e1 * inv;
            atomicAdd(&g_cnt[i0], 1);
            atomicAdd(&g_cnt[i1], 1);
        }
    }
    __syncthreads();
    if (threadIdx.x == 0) {
        __threadfence();
        int prev = atomicAdd(&g_done, 1);
        if (prev == (int)gridDim.x - 1) {           // last block: run the scan
            int off = 0;
            for (int e = 0; e < NE; e++) {
                g_poff[e] = off; g_cursor[e] = off;
                off += ((g_cnt[e] + BM - 1) / BM) * BM;
            }
            g_poff[NE] = off;
            g_ptotal = off;
            __threadfence();
        }
    }
}

__global__ void place_kernel() {
    int id = blockIdx.x * blockDim.x + threadIdx.x;
    if (id >= 2*T_TOK) return;
    int e = g_tok_e[id];
    int r = atomicAdd(&g_cursor[e], 1);
    g_rowtok[r] = id >> 1;
    g_roww[r]   = g_tok_w[id];
    g_tok_slot[id] = r;
}

// 4-wide combine: out += Y[slot0] + Y[slot1]
__global__ void combine_kernel(float* __restrict__ out) {
    int i = blockIdx.x * blockDim.x + threadIdx.x;
    if (i >= T_TOK * DH / 4) return;
    int t = (i * 4) / DH;
    int d = i * 4 - t * DH;
    int s0 = g_tok_slot[2*t], s1 = g_tok_slot[2*t + 1];
    const half2* y0p = (const half2*)&g_Yh[(size_t)s0 * DH + d];
    const half2* y1p = (const half2*)&g_Yh[(size_t)s1 * DH + d];
    float2 a0 = __half22float2(y0p[0]), a1 = __half22float2(y0p[1]);
    float2 b0 = __half22float2(y1p[0]), b1 = __half22float2(y1p[1]);
    float4 o = *(float4*)&out[i * 4];
    o.x += a0.x + b0.x;
    o.y += a0.y + b0.y;
    o.z += a1.x + b1.x;
    o.w += a1.y + b1.y;
    *(float4*)&out[i * 4] = o;
}

// ---------------- merged fp16 mma.sync GEMMs (hoisted loader pointers) ----------------
// PAIR 0 (K=768, LDC=FF):  rm=0: Act = gelu(xh@w1^T+b1)*(xh@w3^T+b3)  [4096 CTAs]
//                          rm=1: Hrh = fp16(gelu(gather(xh)@fc1^T+b)) [264*16 CTAs]
// PAIR 1 (K=2048, LDC=DH): rm=0: out = Acth @ w2^T + b2               [768 CTAs]
//                          rm=1: Yh  = fp16(w*(Hrh @ fc2^T + b))      [264*6 CTAs]
template<int PAIR>
__global__ void __launch_bounds__(NTHR, 2) tgemm(
    const float* __restrict__ bias0, const float* __restrict__ bias1,
    const float* __restrict__ bias2, float* __restrict__ Cpar)
{
    constexpr int K   = (PAIR == 0) ? DH : FF;
    constexpr int LDC = (PAIR == 0) ? FF : DH;
    constexpr int ns  = K / BK;
    constexpr int NSHARED = (PAIR == 0) ? 4096 : 768;   // CTAs in the shared-MLP half

    // decode flattened grid (mtile fastest, matching old 2D-grid CTA order)
    const int bx = blockIdx.x;
    bool rm; int mt, nt;
    if (bx < NSHARED) { rm = false; mt = bx & 127; nt = bx >> 7; }
    else              { rm = true;  int b2 = bx - NSHARED; mt = b2 % MTILES; nt = b2 / MTILES; }

    const int m0 = mt * BM;
    const int n0 = nt * 128;                 // B-tile row offset
    int eidx = 0;
    if (rm) {
        if (m0 >= g_ptotal) return;
        while (m0 >= g_poff[eidx + 1]) eidx++;
    }

    const __half* Ah;
    const __half* Bh = nullptr;
    if (PAIR == 0) {
        Ah = g_xh;
        if (rm) Bh = g_fc1h + (size_t)eidx * FF * DH;
    } else {
        Ah = rm ? g_Hrh : g_Acth;
        Bh = rm ? (g_fc2h + (size_t)eidx * DH * FF) : g_w2h;
    }

    extern __shared__ char dsm[];
    __shared__ int   s_tok [BM];
    __shared__ float s_bias[128];
    __shared__ float s_roww[BM];

    const int tid  = threadIdx.x;
    const int lane = tid & 31;
    const int wid  = tid >> 5;
    const int wm   = wid & 1;                // 2 warps along M (64 rows each)
    const int wn   = wid >> 1;               // 4 warps along N (32 B-rows each)
    const int gid  = lane >> 2;
    const int qid  = lane & 3;

    if (tid < BM) {
        if (PAIR == 0 && rm) s_tok [tid] = g_rowtok[m0 + tid];
        if (PAIR == 1 && rm) s_roww[tid] = g_roww  [m0 + tid];
        if (PAIR == 0) {
            if (!rm) {
                int ng = tid >> 3, odd = ng & 1, gg = ng >> 1;
                int j = nt * 64 + gg * 8 + (tid & 7);
                s_bias[tid] = odd ? bias1[j] : bias0[j];
            } else {
                s_bias[tid] = bias2[eidx * FF + n0 + tid];
            }
        } else {
            s_bias[tid] = rm ? bias2[eidx * DH + n0 + tid] : bias0[n0 + tid];
        }
    }
    __syncthreads();

    const uint32_t smem_base = smem_u32(dsm);

    // -------- hoisted loader state: 8 src pointers + 8 dst swizzle offsets per thread --------
    // Stages load strictly in order; pointers advance by BK halfs per stage.
    const __half* srcp[8];
    uint32_t dsto[8];
#pragma unroll
    for (int i = 0; i < 8; i++) {
        int c = tid + i * NTHR;
        if (c < 1024) {                       // A half (compile-time per unrolled i)
            int r = c >> 3, ch = c & 7;
            int arow = (PAIR == 0 && rm) ? s_tok[r] : (m0 + r);
            srcp[i] = Ah + (size_t)arow * K + ch * 8;
            dsto[i] = (uint32_t)(r * 128 + ((ch ^ (r & 7)) << 4));
        } else {                              // B half
            int c2 = c - 1024;
            int rn = c2 >> 3, ch = c2 & 7;
            if (PAIR == 0 && !rm) {
                int ng = rn >> 3, odd = ng & 1, gg = ng >> 1;
                int j = nt * 64 + gg * 8 + (rn & 7);
                srcp[i] = (odd ? g_w3h : g_w1h) + (size_t)j * DH + ch * 8;
            } else {
                srcp[i] = Bh + (size_t)(n0 + rn) * K + ch * 8;
            }
            dsto[i] = (uint32_t)(16384 + rn * 128 + ((ch ^ (rn & 7)) << 4));
        }
    }
    uint32_t ld_off = 0;                      // rotating stage-buffer offset (producer)
    auto load_stage_adv = [&]() {
        const uint32_t sb = smem_base + ld_off;
#pragma unroll
        for (int i = 0; i < 8; i++) {
            cpa16(sb + dsto[i], srcp[i]);
            srcp[i] += BK;
        }
        ld_off += STAGE_B;
        if (ld_off == NS * STAGE_B) ld_off = 0;
    };

    // per-thread ldmatrix addressing (swizzle XOR term = lane&7 for both A and B)
    const uint32_t x7   = (uint32_t)(lane & 7);
    const uint32_t a_hi = (uint32_t)(lane >> 4);
    const uint32_t b_hi = (uint32_t)((lane >> 3) & 1);
    const uint32_t a_rb = (uint32_t)((wm * 64 + (lane & 15)) * 128);
    const uint32_t b_rb = (uint32_t)(16384 + (wn * 32 + ((lane >> 4) << 3) + (lane & 7)) * 128);

    float acc[4][4][4];
#pragma unroll
    for (int mt2 = 0; mt2 < 4; mt2++)
#pragma unroll
        for (int nt2 = 0; nt2 < 4; nt2++)
#pragma unroll
            for (int r = 0; r < 4; r++) acc[mt2][nt2][r] = 0.0f;

    // ping-pong fragment buffers (kk-pipelined)
    uint32_t af[2][4][4];
    uint32_t bf[2][4][2];

    auto ldf = [&](uint32_t sb, int kk, int pb) {
        const uint32_t aoff = ((((uint32_t)(kk * 2) + a_hi) ^ x7) << 4);
#pragma unroll
        for (int m = 0; m < 4; m++)
            LDSM_X4(af[pb][m][0], af[pb][m][1], af[pb][m][2], af[pb][m][3],
                    sb + a_rb + (uint32_t)(m * 2048) + aoff);
        const uint32_t boff = ((((uint32_t)(kk * 2) + b_hi) ^ x7) << 4);
#pragma unroll
        for (int p = 0; p < 2; p++)
            LDSM_X4(bf[pb][2*p][0], bf[pb][2*p][1], bf[pb][2*p+1][0], bf[pb][2*p+1][1],
                    sb + b_rb + (uint32_t)(p * 2048) + boff);
    };

    load_stage_adv(); cpa_commit();
    load_stage_adv(); cpa_commit();

    uint32_t cs_off = 0;                      // rotating stage-buffer offset (consumer)
    for (int s = 0; s < ns; s++) {
        cpa_wait<NS - 2>();
        __syncthreads();
        if (s + NS - 1 < ns) load_stage_adv();
        cpa_commit();                       // empty-group commit keeps wait semantics in tail

        const uint32_t sb = smem_base + cs_off;
        cs_off += STAGE_B;
        if (cs_off == NS * STAGE_B) cs_off = 0;

        ldf(sb, 0, 0);                      // only exposed LDSM burst this stage
#pragma unroll
        for (int kk = 0; kk < BK / 16; kk++) {
            const int cur = kk & 1;
            if (kk + 1 < BK / 16) ldf(sb, kk + 1, (kk + 1) & 1);   // prefetch next kk
#pragma unroll
            for (int m = 0; m < 4; m++)
#pragma unroll
                for (int n = 0; n < 4; n++)
                    MMA_F16(acc[m][n], af[cur][m], bf[cur][n]);
        }
    }

    // -------- epilogue --------
#pragma unroll
    for (int m = 0; m < 4; m++) {
        const int lr0 = wm * 64 + m * 16 + gid;
        const int lr1 = lr0 + 8;
        const int row0 = m0 + lr0, row1 = m0 + lr1;
        if (PAIR == 0) {
            if (!rm) {
                // gated fused act: pair even/odd n8 groups (h1 from w1 rows, h3 from w3 rows)
#pragma unroll
                for (int g = 0; g < 2; g++) {
                    const int cle = wn * 32 + (2*g) * 8 + qid * 2;
                    const int clo = cle + 8;
                    float b1x = s_bias[cle], b1y = s_bias[cle + 1];
                    float b3x = s_bias[clo], b3y = s_bias[clo + 1];
                    float a00 = gelu_f(acc[m][2*g][0] + b1x) * (acc[m][2*g+1][0] + b3x);
                    float a01 = gelu_f(acc[m][2*g][1] + b1y) * (acc[m][2*g+1][1] + b3y);
                    float a10 = gelu_f(acc[m][2*g][2] + b1x) * (acc[m][2*g+1][2] + b3x);
                    float a11 = gelu_f(acc[m][2*g][3] + b1y) * (acc[m][2*g+1][3] + b3y);
                    const int colj = nt * 64 + (wn * 2 + g) * 8 + qid * 2;
                    *(half2*)&g_Acth[(size_t)row0 * LDC + colj] = __floats2half2_rn(a00, a01);
                    *(half2*)&g_Acth[(size_t)row1 * LDC + colj] = __floats2half2_rn(a10, a11);
                }
            } else {
#pragma unroll
                for (int n = 0; n < 4; n++) {
                    const int cl = wn * 32 + n * 8 + qid * 2;
                    const int col = n0 + cl;
                    float v00 = acc[m][n][0] + s_bias[cl];
                    float v01 = acc[m][n][1] + s_bias[cl + 1];
                    float v10 = acc[m][n][2] + s_bias[cl];
                    float v11 = acc[m][n][3] + s_bias[cl + 1];
                    *(half2*)&g_Hrh[(size_t)row0 * LDC + col] =
                        __floats2half2_rn(gelu_f(v00), gelu_f(v01));
                    *(half2*)&g_Hrh[(size_t)row1 * LDC + col] =
                        __floats2half2_rn(gelu_f(v10), gelu_f(v11));
                }
            }
        } else {
            float wmul0 = 1.0f, wmul1 = 1.0f;
            if (rm) { wmul0 = s_roww[lr0]; wmul1 = s_roww[lr1]; }
#pragma unroll
            for (int n = 0; n < 4; n++) {
                const int cl = wn * 32 + n * 8 + qid * 2;
                const int col = n0 + cl;
                float v00 = acc[m][n][0] + s_bias[cl];
                float v01 = acc[m][n][1] + s_bias[cl + 1];
                float v10 = acc[m][n][2] + s_bias[cl];
                float v11 = acc[m][n][3] + s_bias[cl + 1];
                if (!rm) {
                    *(float2*)&Cpar[(size_t)row0 * LDC + col] = make_float2(v00, v01);
                    *(float2*)&Cpar[(size_t)row1 * LDC + col] = make_float2(v10, v11);
                } else {
                    *(half2*)&g_Yh[(size_t)row0 * LDC + col] =
                        __floats2half2_rn(v00 * wmul0, v01 * wmul0);
                    *(half2*)&g_Yh[(size_t)row1 * LDC + col] =
                        __floats2half2_rn(v10 * wmul1, v11 * wmul1);
                }
            }
        }
    }
}

// ---------------- launch ----------------
extern "C" void kernel_launch(void* const* d_in, const int* in_sizes, int n_in,
                              void* d_out, int out_size) {
    const float* x      = (const float*)d_in[0];
    const float* gate_w = (const float*)d_in[1];
    const float* fc1_b  = (const float*)d_in[3];
    const float* fc2_b  = (const float*)d_in[5];
    const float* w1_b   = (const float*)d_in[7];
    const float* w3_b   = (const float*)d_in[9];
    const float* w2_b   = (const float*)d_in[11];
    float* out = (float*)d_out;

    const int dyn = NS * STAGE_B;     // 98304 bytes -> 2 CTA/SM
    cudaFuncSetAttribute(tgemm<0>, cudaFuncAttributeMaxDynamicSharedMemorySize, dyn);
    cudaFuncSetAttribute(tgemm<1>, cudaFuncAttributeMaxDynamicSharedMemorySize, dyn);

    preconv_kernel<<<2048, 256>>>((const float4*)x, (const float4*)d_in[2],
                                  (const float4*)d_in[4], (const float4*)d_in[6],
                                  (const float4*)d_in[8], (const float4*)d_in[10]);     // 0
    gate_kernel<<<(T_TOK * 32) / 256, 256>>>(x, gate_w);                                // 1 (+scan fused)
    place_kernel<<<(2 * T_TOK) / 256, 256>>>();                                         // 2
    tgemm<0><<<4096 + MTILES * (FF/128), NTHR, dyn>>>(w1_b, w3_b, fc1_b, nullptr);      // 3 (merged fc1s)
    tgemm<1><<<768 + MTILES * (DH/128), NTHR, dyn>>>(w2_b, nullptr, fc2_b, out);        // 4 (merged fc2s)
    combine_kernel<<<(T_TOK * DH / 4) / 256, 256>>>(out);                               // 5
}

// round 16
// speedup vs baseline: 1.4516x; 1.4516x over previous
#include <cuda_runtime.h>
#include <cuda_fp16.h>
#include <math.h>
#include <stdint.h>

#define T_TOK 16384
#define DH 768
#define FF 2048
#define NE 8
#define BM 128
#define BK 64
#define NS 3
#define STAGE_B 32768                 /* A 16KB + B 16KB per stage */
#define NTHR 256                      /* 8 warps, 64x32 warp tile, 2 CTA/SM */
#define MAXROWS (2*T_TOK + NE*BM)     /* 33792 */
#define MTILES  (MAXROWS/BM)          /* 264 */

// ---------------- scratch ----------------
__device__ __align__(256) __half g_Acth[(size_t)T_TOK * FF];
__device__ __align__(256) __half g_Hrh [(size_t)MAXROWS * FF];
__device__ __align__(256) __half g_Yh  [(size_t)MAXROWS * DH];
// fp16 operand copies
__device__ __align__(256) __half g_xh  [(size_t)T_TOK * DH];
__device__ __align__(256) __half g_fc1h[(size_t)NE * FF * DH];
__device__ __align__(256) __half g_fc2h[(size_t)NE * DH * FF];
__device__ __align__(256) __half g_w1h [(size_t)FF * DH];
__device__ __align__(256) __half g_w3h [(size_t)FF * DH];
__device__ __align__(256) __half g_w2h [(size_t)DH * FF];
__device__ int   g_rowtok[MAXROWS];
__device__ float g_roww  [MAXROWS];
__device__ int   g_tok_e [2*T_TOK];
__device__ float g_tok_w [2*T_TOK];
__device__ int   g_tok_slot[2*T_TOK];
__device__ int   g_cnt   [NE];
__device__ int   g_cursor[NE];
__device__ int   g_poff  [NE+1];
__device__ int   g_ptotal;
__device__ int   g_done;

__device__ __forceinline__ float gelu_f(float v) {
    return 0.5f * v * (1.0f + erff(v * 0.7071067811865476f));
}

// ---------------- PTX helpers (sm_75+/sm_80+ only: family-target-safe) ----------------
__device__ __forceinline__ uint32_t smem_u32(const void* p) {
    uint32_t a;
    asm("{ .reg .u64 t; cvta.to.shared.u64 t, %1; cvt.u32.u64 %0, t; }" : "=r"(a) : "l"(p));
    return a;
}
__device__ __forceinline__ void cpa16(uint32_t dst, const void* src) {
    asm volatile("cp.async.cg.shared.global [%0], [%1], 16;" :: "r"(dst), "l"(src));
}
__device__ __forceinline__ void cpa_commit() { asm volatile("cp.async.commit_group;"); }
template<int N> __device__ __forceinline__ void cpa_wait() { asm volatile("cp.async.wait_group %0;" :: "n"(N)); }

#define LDSM_X4(r0, r1, r2, r3, addr) \
    asm volatile("ldmatrix.sync.aligned.m8n8.x4.shared.b16 {%0,%1,%2,%3}, [%4];" \
        : "=r"(r0), "=r"(r1), "=r"(r2), "=r"(r3) : "r"(addr))

#define MMA_F16(d, a, b) \
    asm volatile("mma.sync.aligned.m16n8k16.row.col.f32.f16.f16.f32 " \
        "{%0,%1,%2,%3}, {%4,%5,%6,%7}, {%8,%9}, {%0,%1,%2,%3};" \
        : "+f"((d)[0]), "+f"((d)[1]), "+f"((d)[2]), "+f"((d)[3]) \
        : "r"((a)[0]), "r"((a)[1]), "r"((a)[2]), "r"((a)[3]), "r"((b)[0]), "r"((b)[1]))

// ---------------- small kernels ----------------
// preconv + init fused: fp32 -> fp16 operand conversion + routing-scratch reset.
#define PC_N0 (T_TOK*DH/4)
#define PC_N1 (PC_N0 + NE*FF*DH/4)
#define PC_N2 (PC_N1 + NE*DH*FF/4)
#define PC_N3 (PC_N2 + FF*DH/4)
#define PC_N4 (PC_N3 + FF*DH/4)
#define PC_N5 (PC_N4 + DH*FF/4)
__global__ void preconv_kernel(const float4* __restrict__ x,  const float4* __restrict__ fc1,
                               const float4* __restrict__ fc2, const float4* __restrict__ w1,
                               const float4* __restrict__ w3,  const float4* __restrict__ w2) {
    int g0 = blockIdx.x * blockDim.x + threadIdx.x;
    if (g0 < MAXROWS) { g_rowtok[g0] = 0; g_roww[g0] = 0.0f; }
    if (g0 < NE) g_cnt[g0] = 0;
    if (g0 == 0) g_done = 0;
    for (long i = g0; i < PC_N5; i += (long)gridDim.x * blockDim.x) {
        const float4* src; half2* dst; long j;
        if (i < PC_N0)      { src = x;   dst = (half2*)g_xh;   j = i; }
        else if (i < PC_N1) { src = fc1; dst = (half2*)g_fc1h; j = i - PC_N0; }
        else if (i < PC_N2) { src = fc2; dst = (half2*)g_fc2h; j = i - PC_N1; }
        else if (i < PC_N3) { src = w1;  dst = (half2*)g_w1h;  j = i - PC_N2; }
        else if (i < PC_N4) { src = w3;  dst = (half2*)g_w3h;  j = i - PC_N3; }
        else                { src = w2;  dst = (half2*)g_w2h;  j = i - PC_N4; }
        float4 v = src[j];
        dst[j*2]   = __floats2half2_rn(v.x, v.y);
        dst[j*2+1] = __floats2half2_rn(v.z, v.w);
    }
}

// gate + fused scan (last block computes padded segment offsets)
__global__ void gate_kernel(const float* __restrict__ x, const float* __restrict__ gw) {
    int gtid = blockIdx.x * blockDim.x + threadIdx.x;
    int t = gtid >> 5, lane = gtid & 31;
    if (t < T_TOK) {
        const float* xr = x + (size_t)t * DH;
        float acc[NE];
#pragma unroll
        for (int e = 0; e < NE; e++) acc[e] = 0.0f;
        for (int i = lane; i < DH; i += 32) {
            float xv = xr[i];
#pragma unroll
            for (int e = 0; e < NE; e++) acc[e] = fmaf(xv, gw[e*DH + i], acc[e]);
        }
#pragma unroll
        for (int e = 0; e < NE; e++) {
#pragma unroll
            for (int o = 16; o > 0; o >>= 1) acc[e] += __shfl_xor_sync(0xffffffffu, acc[e], o);
        }
        if (lane == 0) {
            int i0 = 0;
#pragma unroll
            for (int e = 1; e < NE; e++) if (acc[e] > acc[i0]) i0 = e;
            int i1 = (i0 == 0) ? 1 : 0;
#pragma unroll
            for (int e = 0; e < NE; e++) if (e != i0 && acc[e] > acc[i1]) i1 = e;
            float e1 = expf(acc[i1] - acc[i0]);
            float inv = 1.0f / (1.0f + e1);
            g_tok_e[2*t]   = i0;  g_tok_w[2*t]   = inv;
            g_tok_e[2*t+1] = i1;  g_tok_w[2*t+1] = e1 * inv;
            atomicAdd(&g_cnt[i0], 1);
            atomicAdd(&g_cnt[i1], 1);
        }
    }
    __syncthreads();
    if (threadIdx.x == 0) {
        __threadfence();
        int prev = atomicAdd(&g_done, 1);
        if (prev == (int)gridDim.x - 1) {           // last block: run the scan
            int off = 0;
            for (int e = 0; e < NE; e++) {
                g_poff[e] = off; g_cursor[e] = off;
                off += ((g_cnt[e] + BM - 1) / BM) * BM;
            }
            g_poff[NE] = off;
            g_ptotal = off;
            __threadfence();
        }
    }
}

__global__ void place_kernel() {
    int id = blockIdx.x * blockDim.x + threadIdx.x;
    if (id >= 2*T_TOK) return;
    int e = g_tok_e[id];
    int r = atomicAdd(&g_cursor[e], 1);
    g_rowtok[r] = id >> 1;
    g_roww[r]   = g_tok_w[id];
    g_tok_slot[id] = r;
}

// 4-wide combine: out += Y[slot0] + Y[slot1]
__global__ void combine_kernel(float* __restrict__ out) {
    int i = blockIdx.x * blockDim.x + threadIdx.x;
    if (i >= T_TOK * DH / 4) return;
    int t = (i * 4) / DH;
    int d = i * 4 - t * DH;
    int s0 = g_tok_slot[2*t], s1 = g_tok_slot[2*t + 1];
    const half2* y0p = (const half2*)&g_Yh[(size_t)s0 * DH + d];
    const half2* y1p = (const half2*)&g_Yh[(size_t)s1 * DH + d];
    float2 a0 = __half22float2(y0p[0]), a1 = __half22float2(y0p[1]);
    float2 b0 = __half22float2(y1p[0]), b1 = __half22float2(y1p[1]);
    float4 o = *(float4*)&out[i * 4];
    o.x += a0.x + b0.x;
    o.y += a0.y + b0.y;
    o.z += a1.x + b1.x;
    o.w += a1.y + b1.y;
    *(float4*)&out[i * 4] = o;
}

// ---------------- merged fp16 mma.sync GEMMs (32-bit hoisted loader offsets) ----------------
// PAIR 0 (K=768, LDC=FF):  rm=0: Act = gelu(xh@w1^T+b1)*(xh@w3^T+b3)  [4096 CTAs]
//                          rm=1: Hrh = fp16(gelu(gather(xh)@fc1^T+b)) [264*16 CTAs]
// PAIR 1 (K=2048, LDC=DH): rm=0: out = Acth @ w2^T + b2               [768 CTAs]
//                          rm=1: Yh  = fp16(w*(Hrh @ fc2^T + b))      [264*6 CTAs]
template<int PAIR>
__global__ void __launch_bounds__(NTHR, 2) tgemm(
    const float* __restrict__ bias0, const float* __restrict__ bias1,
    const float* __restrict__ bias2, float* __restrict__ Cpar)
{
    constexpr int K   = (PAIR == 0) ? DH : FF;
    constexpr int LDC = (PAIR == 0) ? FF : DH;
    constexpr int ns  = K / BK;
    constexpr int NSHARED = (PAIR == 0) ? 4096 : 768;   // CTAs in the shared-MLP half

    // decode flattened grid (mtile fastest, matching old 2D-grid CTA order)
    const int bx = blockIdx.x;
    bool rm; int mt, nt;
    if (bx < NSHARED) { rm = false; mt = bx & 127; nt = bx >> 7; }
    else              { rm = true;  int b2 = bx - NSHARED; mt = b2 % MTILES; nt = b2 / MTILES; }

    const int m0 = mt * BM;
    const int n0 = nt * 128;                 // B-tile row offset
    int eidx = 0;
    if (rm) {
        if (m0 >= g_ptotal) return;
        while (m0 >= g_poff[eidx + 1]) eidx++;
    }

    const __half* Ah;
    const __half* Bh = nullptr;
    if (PAIR == 0) {
        Ah = g_xh;
        if (rm) Bh = g_fc1h + (size_t)eidx * FF * DH;
    } else {
        Ah = rm ? g_Hrh : g_Acth;
        Bh = rm ? (g_fc2h + (size_t)eidx * DH * FF) : g_w2h;
    }

    extern __shared__ char dsm[];
    __shared__ int   s_tok [BM];
    __shared__ float s_bias[128];
    __shared__ float s_roww[BM];

    const int tid  = threadIdx.x;
    const int lane = tid & 31;
    const int wid  = tid >> 5;
    const int wm   = wid & 1;                // 2 warps along M (64 rows each)
    const int wn   = wid >> 1;               // 4 warps along N (32 B-rows each)
    const int gid  = lane >> 2;
    const int qid  = lane & 3;

    if (tid < BM) {
        if (PAIR == 0 && rm) s_tok [tid] = g_rowtok[m0 + tid];
        if (PAIR == 1 && rm) s_roww[tid] = g_roww  [m0 + tid];
        if (PAIR == 0) {
            if (!rm) {
                int ng = tid >> 3, odd = ng & 1, gg = ng >> 1;
                int j = nt * 64 + gg * 8 + (tid & 7);
                s_bias[tid] = odd ? bias1[j] : bias0[j];
            } else {
                s_bias[tid] = bias2[eidx * FF + n0 + tid];
            }
        } else {
            s_bias[tid] = rm ? bias2[eidx * DH + n0 + tid] : bias0[n0 + tid];
        }
    }
    __syncthreads();

    const uint32_t smem_base = smem_u32(dsm);

    // -------- hoisted loader: per thread ch=tid&7 and rows rbase+32*i for both halves --------
    // dst swizzle term is constant across i ((r&7) invariant) -> ONE dst base per half.
    // In MODE0 interleave, odd=(rbase>>3)&1 is constant per thread -> ONE B base pointer.
    const int ch    = tid & 7;
    const int rbase = tid >> 3;              // 0..31
    const uint32_t dstA = (uint32_t)(rbase * 128 + ((ch ^ (rbase & 7)) << 4));
    const uint32_t dstB = dstA + 16384u;

    const __half* pB;
    uint32_t aoff[4], boff[4];               // 32-bit element offsets, advance += BK per stage
#pragma unroll
    for (int i = 0; i < 4; i++) {
        int r = rbase + 32 * i;
        int arow = (PAIR == 0 && rm) ? s_tok[r] : (m0 + r);
        aoff[i] = (uint32_t)(arow * K + ch * 8);
    }
    if (PAIR == 0 && !rm) {
        pB = (((rbase >> 3) & 1) ? g_w3h : g_w1h);
#pragma unroll
        for (int i = 0; i < 4; i++) {
            int rn = rbase + 32 * i;
            int gg = (rn >> 3) >> 1;
            int j = nt * 64 + gg * 8 + ch;   // rn&7 == ch? no: rn&7 == rbase&7; col idx uses rn&7
            j = nt * 64 + gg * 8 + (rn & 7);
            boff[i] = (uint32_t)(j * DH + ch * 8);
        }
    } else {
        pB = Bh;
#pragma unroll
        for (int i = 0; i < 4; i++) {
            int rn = rbase + 32 * i;
            boff[i] = (uint32_t)((n0 + rn) * K + ch * 8);
        }
    }

    uint32_t ld_off = 0;                     // rotating producer stage offset
    auto load_stage_adv = [&]() {
        const uint32_t sb = smem_base + ld_off;
#pragma unroll
        for (int i = 0; i < 4; i++) {
            cpa16(sb + dstA + (uint32_t)(i * 4096), Ah + aoff[i]);
            aoff[i] += BK;
        }
#pragma unroll
        for (int i = 0; i < 4; i++) {
            cpa16(sb + dstB + (uint32_t)(i * 4096), pB + boff[i]);
            boff[i] += BK;
        }
        ld_off += STAGE_B;
        if (ld_off == NS * STAGE_B) ld_off = 0;
    };

    // per-thread ldmatrix addressing (swizzle XOR term = lane&7 for both A and B)
    const uint32_t x7   = (uint32_t)(lane & 7);
    const uint32_t a_hi = (uint32_t)(lane >> 4);
    const uint32_t b_hi = (uint32_t)((lane >> 3) & 1);
    const uint32_t a_rb = (uint32_t)((wm * 64 + (lane & 15)) * 128);
    const uint32_t b_rb = (uint32_t)(16384 + (wn * 32 + ((lane >> 4) << 3) + (lane & 7)) * 128);

    float acc[4][4][4];
#pragma unroll
    for (int mt2 = 0; mt2 < 4; mt2++)
#pragma unroll
        for (int nt2 = 0; nt2 < 4; nt2++)
#pragma unroll
            for (int r = 0; r < 4; r++) acc[mt2][nt2][r] = 0.0f;

    // single fragment buffer (ping-pong dropped to fund loader registers)
    uint32_t af[4][4];
    uint32_t bf[4][2];

    auto ldf = [&](uint32_t sb, int kk) {
        const uint32_t aoff2 = ((((uint32_t)(kk * 2) + a_hi) ^ x7) << 4);
#pragma unroll
        for (int m = 0; m < 4; m++)
            LDSM_X4(af[m][0], af[m][1], af[m][2], af[m][3],
                    sb + a_rb + (uint32_t)(m * 2048) + aoff2);
        const uint32_t boff2 = ((((uint32_t)(kk * 2) + b_hi) ^ x7) << 4);
#pragma unroll
        for (int p = 0; p < 2; p++)
            LDSM_X4(bf[2*p][0], bf[2*p][1], bf[2*p+1][0], bf[2*p+1][1],
                    sb + b_rb + (uint32_t)(p * 2048) + boff2);
    };

    load_stage_adv(); cpa_commit();
    load_stage_adv(); cpa_commit();

    uint32_t cs_off = 0;                     // rotating consumer stage offset
    for (int s = 0; s < ns; s++) {
        cpa_wait<NS - 2>();
        __syncthreads();
        if (s + NS - 1 < ns) load_stage_adv();
        cpa_commit();                       // empty-group commit keeps wait semantics in tail

        const uint32_t sb = smem_base + cs_off;
        cs_off += STAGE_B;
        if (cs_off == NS * STAGE_B) cs_off = 0;

#pragma unroll
        for (int kk = 0; kk < BK / 16; kk++) {
            ldf(sb, kk);
#pragma unroll
            for (int m = 0; m < 4; m++)
#pragma unroll
                for (int n = 0; n < 4; n++)
                    MMA_F16(acc[m][n], af[m], bf[n]);
        }
    }

    // -------- epilogue --------
#pragma unroll
    for (int m = 0; m < 4; m++) {
        const int lr0 = wm * 64 + m * 16 + gid;
        const int lr1 = lr0 + 8;
        const int row0 = m0 + lr0, row1 = m0 + lr1;
        if (PAIR == 0) {
            if (!rm) {
                // gated fused act: pair even/odd n8 groups (h1 from w1 rows, h3 from w3 rows)
#pragma unroll
                for (int g = 0; g < 2; g++) {
                    const int cle = wn * 32 + (2*g) * 8 + qid * 2;
                    const int clo = cle + 8;
                    float b1x = s_bias[cle], b1y = s_bias[cle + 1];
                    float b3x = s_bias[clo], b3y = s_bias[clo + 1];
                    float a00 = gelu_f(acc[m][2*g][0] + b1x) * (acc[m][2*g+1][0] + b3x);
                    float a01 = gelu_f(acc[m][2*g][1] + b1y) * (acc[m][2*g+1][1] + b3y);
                    float a10 = gelu_f(acc[m][2*g][2] + b1x) * (acc[m][2*g+1][2] + b3x);
                    float a11 = gelu_f(acc[m][2*g][3] + b1y) * (acc[m][2*g+1][3] + b3y);
                    const int colj = nt * 64 + (wn * 2 + g) * 8 + qid * 2;
                    *(half2*)&g_Acth[(size_t)row0 * LDC + colj] = __floats2half2_rn(a00, a01);
                    *(half2*)&g_Acth[(size_t)row1 * LDC + colj] = __floats2half2_rn(a10, a11);
                }
            } else {
#pragma unroll
                for (int n = 0; n < 4; n++) {
                    const int cl = wn * 32 + n * 8 + qid * 2;
                    const int col = n0 + cl;
                    float v00 = acc[m][n][0] + s_bias[cl];
                    float v01 = acc[m][n][1] + s_bias[cl + 1];
                    float v10 = acc[m][n][2] + s_bias[cl];
                    float v11 = acc[m][n][3] + s_bias[cl + 1];
                    *(half2*)&g_Hrh[(size_t)row0 * LDC + col] =
                        __floats2half2_rn(gelu_f(v00), gelu_f(v01));
                    *(half2*)&g_Hrh[(size_t)row1 * LDC + col] =
                        __floats2half2_rn(gelu_f(v10), gelu_f(v11));
                }
            }
        } else {
            float wmul0 = 1.0f, wmul1 = 1.0f;
            if (rm) { wmul0 = s_roww[lr0]; wmul1 = s_roww[lr1]; }
#pragma unroll
            for (int n = 0; n < 4; n++) {
                const int cl = wn * 32 + n * 8 + qid * 2;
                const int col = n0 + cl;
                float v00 = acc[m][n][0] + s_bias[cl];
                float v01 = acc[m][n][1] + s_bias[cl + 1];
                float v10 = acc[m][n][2] + s_bias[cl];
                float v11 = acc[m][n][3] + s_bias[cl + 1];
                if (!rm) {
                    *(float2*)&Cpar[(size_t)row0 * LDC + col] = make_float2(v00, v01);
                    *(float2*)&Cpar[(size_t)row1 * LDC + col] = make_float2(v10, v11);
                } else {
                    *(half2*)&g_Yh[(size_t)row0 * LDC + col] =
                        __floats2half2_rn(v00 * wmul0, v01 * wmul0);
                    *(half2*)&g_Yh[(size_t)row1 * LDC + col] =
                        __floats2half2_rn(v10 * wmul1, v11 * wmul1);
                }
            }
        }
    }
}

// ---------------- launch ----------------
extern "C" void kernel_launch(void* const* d_in, const int* in_sizes, int n_in,
                              void* d_out, int out_size) {
    const float* x      = (const float*)d_in[0];
    const float* gate_w = (const float*)d_in[1];
    const float* fc1_b  = (const float*)d_in[3];
    const float* fc2_b  = (const float*)d_in[5];
    const float* w1_b   = (const float*)d_in[7];
    const float* w3_b   = (const float*)d_in[9];
    const float* w2_b   = (const float*)d_in[11];
    float* out = (float*)d_out;

    const int dyn = NS * STAGE_B;     // 98304 bytes -> 2 CTA/SM
    cudaFuncSetAttribute(tgemm<0>, cudaFuncAttributeMaxDynamicSharedMemorySize, dyn);
    cudaFuncSetAttribute(tgemm<1>, cudaFuncAttributeMaxDynamicSharedMemorySize, dyn);

    preconv_kernel<<<2048, 256>>>((const float4*)x, (const float4*)d_in[2],
                                  (const float4*)d_in[4], (const float4*)d_in[6],
                                  (const float4*)d_in[8], (const float4*)d_in[10]);     // 0
    gate_kernel<<<(T_TOK * 32) / 256, 256>>>(x, gate_w);                                // 1 (+scan fused)
    place_kernel<<<(2 * T_TOK) / 256, 256>>>();                                         // 2
    tgemm<0><<<4096 + MTILES * (FF/128), NTHR, dyn>>>(w1_b, w3_b, fc1_b, nullptr);      // 3 (merged fc1s)
    tgemm<1><<<768 + MTILES * (DH/128), NTHR, dyn>>>(w2_b, nullptr, fc2_b, out);        // 4 (merged fc2s)
    combine_kernel<<<(T_TOK * DH / 4) / 256, 256>>>(out);                               // 5
}